// round 1
// baseline (speedup 1.0000x reference)
#include <cuda_runtime.h>
#include <math.h>

#define D 256
#define HW 4096
#define NQ 300
#define NP 8
#define KP1 2304
#define NLAY 6

// ---------------- scratch (device globals; no allocation) ----------------
__device__ float g_Wc[D * 512];        // combined temporal+input-proj weights, [n][s*128+i]
__device__ float g_biasc[D];
__device__ float g_wt[9 * D * D];      // repacked conv weights [tap][c][o]
__device__ float g_x[2 * HW * D];      // x256 + pos, channel-last (b,hw,d)
__device__ float g_y[2 * HW * D];      // lateral out
__device__ float g_f0[2 * HW * D];     // conv out (scale-1 feature map), channel-last
__device__ float g_q[2 * NQ * D];      // queries
__device__ float g_h1[2 * NQ * D];
__device__ float g_ref[2 * NQ * NP * 2];
__device__ float g_flat[2 * NQ * NP * KP1];
__device__ float g_pv1[2 * NQ * NP * D];
__device__ float g_pv2[2 * NQ * NP * D];
__device__ float g_kv[2 * NQ * D];
__device__ float g_kvT[2 * D * NQ];
__device__ float g_qp[2 * NQ * D];
__device__ float g_sc[2 * NQ * NQ];
__device__ float g_ao[2 * NQ * D];
__device__ float g_hb[2 * NQ * D];
__device__ float g_boxes[2 * NQ * 4];

// ---------------- prep kernels ----------------
// Fold temporal conv (k=3,pad=1) + mean over T=4 + input proj into one weight.
// mean_t conv => per-source-frame coeffs: s0: w0+w1 ; s1,s2: w0+w1+w2 ; s3: w1+w2
__global__ void prep_wc(const float* __restrict__ w_tf, const float* __restrict__ b_tf,
                        const float* __restrict__ w_in, const float* __restrict__ b_in) {
    int idx = blockIdx.x * blockDim.x + threadIdx.x;
    if (idx < 4 * D * 128) {
        int s = idx >> 15;
        int r = idx & 32767;
        int n = r >> 7;
        int i = r & 127;
        float acc = 0.f;
        for (int c = 0; c < 128; c++) {
            const float* w3 = w_tf + (c * 128 + i) * 3;
            float coeff;
            if (s == 0)      coeff = w3[0] + w3[1];
            else if (s == 3) coeff = w3[1] + w3[2];
            else             coeff = w3[0] + w3[1] + w3[2];
            acc += w_in[n * 128 + c] * coeff;
        }
        g_Wc[n * 512 + s * 128 + i] = 0.25f * acc;
    }
    if (idx < D) {
        float a = b_in[idx];
        for (int c = 0; c < 128; c++) a += w_in[idx * 128 + c] * b_tf[c];
        g_biasc[idx] = a;
    }
}

// repack w_sm[0] (O,C,3,3) -> [tap][c][o] for coalesced B-tile loads in conv
__global__ void prep_wt(const float* __restrict__ w_sm) {
    int idx = blockIdx.x * blockDim.x + threadIdx.x;
    if (idx >= 9 * D * D) return;
    int tap = idx / (D * D);
    int r = idx % (D * D);
    int c = r / D;
    int o = r % D;
    g_wt[idx] = w_sm[(o * D + c) * 9 + tap];
}

// ---------------- stage A: feat -> x256 (+bias +sine pos) ----------------
// GEMM M=8192 (b,hw), K=512 (s,i), N=256. A loaded straight from feat (coalesced over hw).
__global__ void stageA(const float* __restrict__ feat) {
    int m0 = blockIdx.x * 64;
    int n0 = blockIdx.y * 64;
    int b = m0 >> 12;
    int hw0 = m0 & (HW - 1);
    int tid = threadIdx.x;
    int tx = tid & 15, ty = tid >> 4;
    __shared__ float As[16][66];
    __shared__ float Bs[16][66];
    float acc[4][4] = {};
    const float* fb = feat + (long long)b * 4 * 128 * HW;
    for (int k0 = 0; k0 < 512; k0 += 16) {
#pragma unroll
        for (int t = 0; t < 4; t++) {
            int lin = tid + t * 256;
            {
                int mm = lin & 63, kk = lin >> 6;
                As[kk][mm] = fb[(long long)(k0 + kk) * HW + hw0 + mm];
            }
            {
                int kk = lin & 15, rr = lin >> 4;
                Bs[kk][rr] = g_Wc[(n0 + rr) * 512 + k0 + kk];
            }
        }
        __syncthreads();
#pragma unroll
        for (int kk = 0; kk < 16; kk++) {
            float a[4], bb[4];
#pragma unroll
            for (int i = 0; i < 4; i++) a[i] = As[kk][ty * 4 + i];
#pragma unroll
            for (int j = 0; j < 4; j++) bb[j] = Bs[kk][tx * 4 + j];
#pragma unroll
            for (int i = 0; i < 4; i++)
#pragma unroll
                for (int j = 0; j < 4; j++) acc[i][j] += a[i] * bb[j];
        }
        __syncthreads();
    }
#pragma unroll
    for (int i = 0; i < 4; i++) {
        int hw = hw0 + ty * 4 + i;
        int h = hw >> 6, w = hw & 63;
#pragma unroll
        for (int j = 0; j < 4; j++) {
            int d = n0 + tx * 4 + j;
            int e = (d < 128) ? d : (d - 128);
            int ii = e >> 1;
            float fl = (float)(ii >> 1);
            float dimt = powf(10000.f, fl * (1.f / 32.f));
            float coord = (d < 128) ? (float)(h + 1) : (float)(w + 1);
            float arg = coord * (6.2831853071795864769f / (64.f + 1e-6f)) / dimt;
            float pv = (e & 1) ? cosf(arg) : sinf(arg);
            g_x[((long long)b * HW + hw) * D + d] = acc[i][j] + g_biasc[d] + pv;
        }
    }
}

// ---------------- generic tiled SGEMM: C = act(alpha*A*W^T + bias) ----------------
__global__ void gemm_k(const float* __restrict__ A, const float* __restrict__ W,
                       const float* __restrict__ bias, float* __restrict__ C,
                       int M, int N, int K, float alpha, int act, int accum,
                       long long sA, long long sW, long long sC) {
    int bz = blockIdx.z;
    A += (long long)bz * sA;
    W += (long long)bz * sW;
    C += (long long)bz * sC;
    int m0 = blockIdx.x * 64;
    int n0 = blockIdx.y * 64;
    int tid = threadIdx.x;
    int tx = tid & 15, ty = tid >> 4;
    __shared__ float As[16][66];
    __shared__ float Bs[16][66];
    float acc[4][4] = {};
    for (int k0 = 0; k0 < K; k0 += 16) {
#pragma unroll
        for (int t = 0; t < 4; t++) {
            int lin = tid + t * 256;
            int kk = lin & 15, rr = lin >> 4;
            int k = k0 + kk;
            int m = m0 + rr;
            As[kk][rr] = (m < M && k < K) ? A[(long long)m * K + k] : 0.f;
            int n = n0 + rr;
            Bs[kk][rr] = (n < N && k < K) ? W[(long long)n * K + k] : 0.f;
        }
        __syncthreads();
#pragma unroll
        for (int kk = 0; kk < 16; kk++) {
            float a[4], bb[4];
#pragma unroll
            for (int i = 0; i < 4; i++) a[i] = As[kk][ty * 4 + i];
#pragma unroll
            for (int j = 0; j < 4; j++) bb[j] = Bs[kk][tx * 4 + j];
#pragma unroll
            for (int i = 0; i < 4; i++)
#pragma unroll
                for (int j = 0; j < 4; j++) acc[i][j] += a[i] * bb[j];
        }
        __syncthreads();
    }
#pragma unroll
    for (int i = 0; i < 4; i++) {
        int m = m0 + ty * 4 + i;
        if (m >= M) continue;
#pragma unroll
        for (int j = 0; j < 4; j++) {
            int n = n0 + tx * 4 + j;
            if (n >= N) continue;
            float v = acc[i][j] * alpha;
            if (bias) v += bias[n];
            if (act == 1) v = fmaxf(v, 0.f);
            if (accum) C[(long long)m * N + n] += v;
            else       C[(long long)m * N + n] = v;
        }
    }
}

// ---------------- 3x3 conv (channel-last), 9 shifted GEMM taps ----------------
__global__ void conv3x3(const float* __restrict__ bias) {
    int n0 = blockIdx.x * 64;
    int h = blockIdx.y;
    int b = blockIdx.z;
    int tid = threadIdx.x;
    int tx = tid & 15, ty = tid >> 4;
    __shared__ float As[16][66];
    __shared__ float Bs[16][66];
    float acc[4][4] = {};
    const float* yb = g_y + (long long)b * HW * D;
    for (int ky = -1; ky <= 1; ky++) {
        int hh = h + ky;
        if ((unsigned)hh >= 64u) continue;
        const float* yrow = yb + (long long)hh * 64 * D;
        for (int kx = -1; kx <= 1; kx++) {
            int tap = (ky + 1) * 3 + (kx + 1);
            const float* wtap = g_wt + tap * D * D;
            for (int c0 = 0; c0 < D; c0 += 16) {
#pragma unroll
                for (int t = 0; t < 4; t++) {
                    int lin = tid + t * 256;
                    {
                        int kk = lin & 15, mm = lin >> 4;
                        int ww = mm + kx;
                        As[kk][mm] = ((unsigned)ww < 64u) ? yrow[ww * D + c0 + kk] : 0.f;
                    }
                    {
                        int nn = lin & 63, kk = lin >> 6;
                        Bs[kk][nn] = wtap[(c0 + kk) * D + n0 + nn];
                    }
                }
                __syncthreads();
#pragma unroll
                for (int kk = 0; kk < 16; kk++) {
                    float a[4], bb[4];
#pragma unroll
                    for (int i = 0; i < 4; i++) a[i] = As[kk][ty * 4 + i];
#pragma unroll
                    for (int j = 0; j < 4; j++) bb[j] = Bs[kk][tx * 4 + j];
#pragma unroll
                    for (int i = 0; i < 4; i++)
#pragma unroll
                        for (int j = 0; j < 4; j++) acc[i][j] += a[i] * bb[j];
                }
                __syncthreads();
            }
        }
    }
#pragma unroll
    for (int i = 0; i < 4; i++) {
        int w = ty * 4 + i;
#pragma unroll
        for (int j = 0; j < 4; j++) {
            int n = n0 + tx * 4 + j;
            g_f0[(((long long)b * 64 + h) * 64 + w) * D + n] = acc[i][j] + bias[n];
        }
    }
}

// ---------------- decoder small kernels ----------------
__global__ void init_q(const float* __restrict__ qe, const float* __restrict__ qp) {
    int idx = blockIdx.x * blockDim.x + threadIdx.x;
    if (idx >= 2 * NQ * D) return;
    int qd = idx % (NQ * D);
    g_q[idx] = qe[qd] + qp[qd];
}

__global__ void init_boxes(const float* __restrict__ pbi) {
    int idx = blockIdx.x * blockDim.x + threadIdx.x;
    if (idx < 2 * NQ * 4) g_boxes[idx] = pbi[idx];
}

// ro = tanh(h1 @ w_r2^T + b_r2); ref = clip(box[:2] + 0.5*ro, 0, 1)
__global__ void roref_kernel(const float* __restrict__ w_r2, const float* __restrict__ b_r2) {
    int bq = blockIdx.x;
    int tid = threadIdx.x;  // 128
    __shared__ float hrow[256];
    __shared__ float ro[16];
    hrow[tid] = g_h1[bq * 256 + tid];
    hrow[tid + 128] = g_h1[bq * 256 + tid + 128];
    __syncthreads();
    int warp = tid >> 5, lane = tid & 31;
#pragma unroll
    for (int jj = 0; jj < 4; jj++) {
        int j = warp * 4 + jj;
        float s = 0.f;
        for (int k = lane; k < 256; k += 32) s += hrow[k] * w_r2[j * 256 + k];
#pragma unroll
        for (int o = 16; o; o >>= 1) s += __shfl_xor_sync(0xffffffffu, s, o);
        if (lane == 0) ro[j] = tanhf(s + b_r2[j]);
    }
    __syncthreads();
    if (tid < 8) {
        float bx = g_boxes[bq * 4 + 0], by = g_boxes[bq * 4 + 1];
        float rx = fminf(fmaxf(bx + 0.5f * ro[2 * tid + 0], 0.f), 1.f);
        float ry = fminf(fmaxf(by + 0.5f * ro[2 * tid + 1], 0.f), 1.f);
        g_ref[(bq * 8 + tid) * 2 + 0] = rx;
        g_ref[(bq * 8 + tid) * 2 + 1] = ry;
    }
}

// bilinear-sample 3x3 patch x 256 ch per (b,q,p) from channel-last f0
__global__ void sample_kernel() {
    int bqp = blockIdx.x;      // 4800
    int c = threadIdx.x;       // 256
    int b = bqp / (NQ * NP);
    float rx = g_ref[bqp * 2 + 0];
    float ry = g_ref[bqp * 2 + 1];
    const float* f = g_f0 + (long long)b * HW * D;
    float* outp = g_flat + (long long)bqp * KP1;
#pragma unroll
    for (int cy = 0; cy < 3; cy++) {
        float oy = (float)(cy - 1);
        float gy = ry * 2.f - 1.f + oy * (2.f / 64.f);
        float yy = fminf(fmaxf((gy + 1.f) * 0.5f * 63.f, 0.f), 63.f);
        float y0f = floorf(yy);
        int y0 = (int)y0f;
        float wy = yy - y0f;
        int y1 = min(y0 + 1, 63);
#pragma unroll
        for (int cx = 0; cx < 3; cx++) {
            float ox = (float)(cx - 1);
            float gx = rx * 2.f - 1.f + ox * (2.f / 64.f);
            float xx = fminf(fmaxf((gx + 1.f) * 0.5f * 63.f, 0.f), 63.f);
            float x0f = floorf(xx);
            int x0 = (int)x0f;
            float wx = xx - x0f;
            int x1 = min(x0 + 1, 63);
            float v00 = f[((y0 << 6) + x0) * D + c];
            float v01 = f[((y0 << 6) + x1) * D + c];
            float v10 = f[((y1 << 6) + x0) * D + c];
            float v11 = f[((y1 << 6) + x1) * D + c];
            float v = v00 * (1.f - wx) * (1.f - wy) + v01 * wx * (1.f - wy)
                    + v10 * (1.f - wx) * wy + v11 * wx * wy;
            outp[(cy * 3 + cx) * D + c] = v;
        }
    }
}

__global__ void kvmean_kernel() {
    int bq = blockIdx.x;   // 600
    int d = threadIdx.x;   // 256
    float s = 0.f;
#pragma unroll
    for (int p = 0; p < 8; p++) s += g_pv2[((long long)bq * 8 + p) * D + d];
    s *= 0.125f;
    g_kv[bq * D + d] = s;
    int b = bq / NQ, qq = bq % NQ;
    g_kvT[((long long)b * D + d) * NQ + qq] = s;
}

__global__ void softmax_kernel() {
    int row = blockIdx.x;  // 600
    float* p = g_sc + (long long)row * NQ;
    int tid = threadIdx.x; // 128
    __shared__ float red[128];
    float m = -1e30f;
    for (int i = tid; i < NQ; i += 128) m = fmaxf(m, p[i]);
    red[tid] = m;
    __syncthreads();
    for (int s = 64; s; s >>= 1) {
        if (tid < s) red[tid] = fmaxf(red[tid], red[tid + s]);
        __syncthreads();
    }
    m = red[0];
    __syncthreads();
    float sum = 0.f;
    for (int i = tid; i < NQ; i += 128) {
        float e = expf(p[i] - m);
        p[i] = e;
        sum += e;
    }
    red[tid] = sum;
    __syncthreads();
    for (int s = 64; s; s >>= 1) {
        if (tid < s) red[tid] += red[tid + s];
        __syncthreads();
    }
    float inv = 1.f / red[0];
    for (int i = tid; i < NQ; i += 128) p[i] *= inv;
}

__global__ void boxupd_kernel(const float* __restrict__ w_b2, const float* __restrict__ b_b2) {
    int bq = blockIdx.x;
    int tid = threadIdx.x;  // 128
    __shared__ float hrow[256];
    hrow[tid] = g_hb[bq * 256 + tid];
    hrow[tid + 128] = g_hb[bq * 256 + tid + 128];
    __syncthreads();
    int warp = tid >> 5, lane = tid & 31;
    float s = 0.f;
    for (int k = lane; k < 256; k += 32) s += hrow[k] * w_b2[warp * 256 + k];
#pragma unroll
    for (int o = 16; o; o >>= 1) s += __shfl_xor_sync(0xffffffffu, s, o);
    if (lane == 0) {
        float delta = 1.f / (1.f + expf(-(s + b_b2[warp])));
        float nb = g_boxes[bq * 4 + warp] + 0.1f * tanhf(delta - 0.5f);
        g_boxes[bq * 4 + warp] = fminf(fmaxf(nb, 0.f), 1.f);
    }
}

__global__ void cls_kernel(const float* __restrict__ w_cls, const float* __restrict__ b_cls,
                           float* __restrict__ out) {
    int bq = blockIdx.x;
    int lane = threadIdx.x;  // 32
    float s = 0.f;
    for (int k = lane; k < 256; k += 32) s += g_q[bq * 256 + k] * w_cls[k];
#pragma unroll
    for (int o = 16; o; o >>= 1) s += __shfl_xor_sync(0xffffffffu, s, o);
    if (lane == 0) out[bq] = s + b_cls[0];
}

__global__ void copy_boxes(float* __restrict__ out) {
    int idx = blockIdx.x * blockDim.x + threadIdx.x;
    if (idx < 2 * NQ * 4) out[600 + idx] = g_boxes[idx];
}

// ---------------- host ----------------
static void gemm(const float* A, const float* W, const float* bias, float* C,
                 int M, int N, int K, float alpha, int act, int accum,
                 int batch, long long sA, long long sW, long long sC) {
    dim3 grid((M + 63) / 64, (N + 63) / 64, batch);
    gemm_k<<<grid, 256>>>(A, W, bias, C, M, N, K, alpha, act, accum, sA, sW, sC);
}

extern "C" void kernel_launch(void* const* d_in, const int* in_sizes, int n_in,
                              void* d_out, int out_size) {
    const float* feat   = (const float*)d_in[0];
    const float* pbi    = (const float*)d_in[1];
    const float* w_tf   = (const float*)d_in[2];
    const float* b_tf   = (const float*)d_in[3];
    const float* w_in   = (const float*)d_in[4];
    const float* b_in   = (const float*)d_in[5];
    const float* w_lat  = (const float*)d_in[6];
    const float* b_lat  = (const float*)d_in[7];
    const float* w_sm   = (const float*)d_in[8];
    const float* b_sm   = (const float*)d_in[9];
    const float* q_embed= (const float*)d_in[10];
    const float* q_pos  = (const float*)d_in[11];
    const float* Wq     = (const float*)d_in[12];
    const float* bqv    = (const float*)d_in[13];
    const float* Wo     = (const float*)d_in[14];
    const float* bo     = (const float*)d_in[15];
    const float* Wp1    = (const float*)d_in[16];
    const float* bp1    = (const float*)d_in[17];
    const float* Wp2    = (const float*)d_in[18];
    const float* bp2    = (const float*)d_in[19];
    const float* w_r1   = (const float*)d_in[20];
    const float* b_r1   = (const float*)d_in[21];
    const float* w_r2   = (const float*)d_in[22];
    const float* b_r2   = (const float*)d_in[23];
    const float* w_b1   = (const float*)d_in[24];
    const float* b_b1   = (const float*)d_in[25];
    const float* w_b2   = (const float*)d_in[26];
    const float* b_b2   = (const float*)d_in[27];
    const float* w_cls  = (const float*)d_in[28];
    const float* b_cls  = (const float*)d_in[29];
    float* out = (float*)d_out;

    float *p_x, *p_y, *p_q, *p_h1, *p_flat, *p_pv1, *p_pv2, *p_kv, *p_kvT, *p_qp, *p_sc, *p_ao, *p_hb;
    cudaGetSymbolAddress((void**)&p_x, g_x);
    cudaGetSymbolAddress((void**)&p_y, g_y);
    cudaGetSymbolAddress((void**)&p_q, g_q);
    cudaGetSymbolAddress((void**)&p_h1, g_h1);
    cudaGetSymbolAddress((void**)&p_flat, g_flat);
    cudaGetSymbolAddress((void**)&p_pv1, g_pv1);
    cudaGetSymbolAddress((void**)&p_pv2, g_pv2);
    cudaGetSymbolAddress((void**)&p_kv, g_kv);
    cudaGetSymbolAddress((void**)&p_kvT, g_kvT);
    cudaGetSymbolAddress((void**)&p_qp, g_qp);
    cudaGetSymbolAddress((void**)&p_sc, g_sc);
    cudaGetSymbolAddress((void**)&p_ao, g_ao);
    cudaGetSymbolAddress((void**)&p_hb, g_hb);

    // backbone (only scale-1 FPN branch is live)
    prep_wc<<<(4 * D * 128 + 255) / 256, 256>>>(w_tf, b_tf, w_in, b_in);
    prep_wt<<<(9 * D * D + 255) / 256, 256>>>(w_sm);
    stageA<<<dim3(128, 4), 256>>>(feat);
    gemm(p_x, w_lat, b_lat, p_y, 2 * HW, D, D, 1.f, 0, 0, 1, 0, 0, 0);
    conv3x3<<<dim3(4, 64, 2), 256>>>(b_sm);

    init_q<<<(2 * NQ * D + 255) / 256, 256>>>(q_embed, q_pos);
    init_boxes<<<(2 * NQ * 4 + 255) / 256, 256>>>(pbi);

    const float inv_sqrt_d = 0.0625f;  // 1/sqrt(256)
    for (int l = 0; l < NLAY; l++) {
        gemm(p_q, w_r1, b_r1, p_h1, 2 * NQ, D, D, 1.f, 1, 0, 1, 0, 0, 0);
        roref_kernel<<<2 * NQ, 128>>>(w_r2, b_r2);
        sample_kernel<<<2 * NQ * NP, 256>>>();
        gemm(p_flat, Wp1 + (long long)l * D * KP1, bp1 + l * D, p_pv1,
             2 * NQ * NP, D, KP1, 1.f, 1, 0, 1, 0, 0, 0);
        gemm(p_pv1, Wp2 + (long long)l * D * D, bp2 + l * D, p_pv2,
             2 * NQ * NP, D, D, 1.f, 0, 0, 1, 0, 0, 0);
        kvmean_kernel<<<2 * NQ, 256>>>();
        gemm(p_q, Wq + (long long)l * D * D, bqv + l * D, p_qp,
             2 * NQ, D, D, 1.f, 0, 0, 1, 0, 0, 0);
        gemm(p_qp, p_kv, nullptr, p_sc, NQ, NQ, D, inv_sqrt_d, 0, 0,
             2, (long long)NQ * D, (long long)NQ * D, (long long)NQ * NQ);
        softmax_kernel<<<2 * NQ, 128>>>();
        gemm(p_sc, p_kvT, nullptr, p_ao, NQ, D, NQ, 1.f, 0, 0,
             2, (long long)NQ * NQ, (long long)D * NQ, (long long)NQ * D);
        gemm(p_ao, Wo + (long long)l * D * D, bo + l * D, p_q,
             2 * NQ, D, D, 1.f, 0, 1 /*accum*/, 1, 0, 0, 0);
        gemm(p_q, w_b1, b_b1, p_hb, 2 * NQ, D, D, 1.f, 1, 0, 1, 0, 0, 0);
        boxupd_kernel<<<2 * NQ, 128>>>(w_b2, b_b2);
    }

    cls_kernel<<<2 * NQ, 32>>>(w_cls, b_cls, out);
    copy_boxes<<<(2 * NQ * 4 + 255) / 256, 256>>>(out);
}

// round 2
// speedup vs baseline: 1.3250x; 1.3250x over previous
#include <cuda_runtime.h>
#include <math.h>
#include <stdint.h>

#define D 256
#define HW 4096
#define NQ 300
#define NP 8
#define KP1 2304
#define NLAY 6

// ---------------- scratch (device globals; no allocation) ----------------
__device__ float g_Wc[D * 512];        // combined temporal+input-proj weights, [n][s*128+i]
__device__ float g_biasc[D];
__device__ float g_wt[KP1 * D];        // repacked conv weights [o][tap*256+c]
__device__ float g_xin[2 * HW * 512];  // transposed stageA input [b*hw][512]
__device__ float g_x[2 * HW * D];      // x256 + pos, channel-last (b,hw,d)
__device__ float g_y[2 * HW * D];      // lateral out
__device__ float g_col[2 * HW * KP1];  // im2col of g_y
__device__ float g_f0[2 * HW * D];     // conv out (scale-1 feature), channel-last
__device__ float g_q[2 * NQ * D];
__device__ float g_h1[2 * NQ * D];
__device__ float g_ref[2 * NQ * NP * 2];
__device__ float g_flat[2 * NQ * NP * KP1];
__device__ float g_pv1[2 * NQ * NP * D];
__device__ float g_pv2[2 * NQ * NP * D];
__device__ float g_kv[2 * NQ * D];
__device__ float g_kvT[2 * D * NQ];
__device__ float g_qp[2 * NQ * D];
__device__ float g_sc[2 * NQ * NQ];
__device__ float g_ao[2 * NQ * D];
__device__ float g_hb[2 * NQ * D];
__device__ float g_boxes[2 * NQ * 4];

// ---------------- tf32 helpers ----------------
__device__ __forceinline__ uint32_t f2tf32(float f) {
    uint32_t u;
    asm("cvt.rna.tf32.f32 %0, %1;" : "=r"(u) : "f"(f));
    return u;
}
__device__ __forceinline__ void split_tf32(float v, uint32_t& hi, uint32_t& lo) {
    hi = f2tf32(v);
    float r = v - __uint_as_float(hi);
    lo = f2tf32(r);
}
__device__ __forceinline__ void mma_tf32(float* c, const uint32_t* a, const uint32_t* b) {
    asm volatile(
        "mma.sync.aligned.m16n8k8.row.col.f32.tf32.tf32.f32 "
        "{%0,%1,%2,%3},{%4,%5,%6,%7},{%8,%9},{%0,%1,%2,%3};"
        : "+f"(c[0]), "+f"(c[1]), "+f"(c[2]), "+f"(c[3])
        : "r"(a[0]), "r"(a[1]), "r"(a[2]), "r"(a[3]), "r"(b[0]), "r"(b[1]));
}

// ---------------- tensor-core GEMM: C = act(alpha*A*W^T + bias) ----------------
// A[M,K] row-major, W[N,K] row-major. tf32x3 (near-fp32). Block tile 128x64, 8 warps.
__global__ void tc_gemm(const float* __restrict__ A, const float* __restrict__ W,
                        const float* __restrict__ bias, float* __restrict__ C,
                        int M, int N, int K, float alpha, int act, int accum,
                        long long sA, long long sW, long long sC) {
    A += (long long)blockIdx.z * sA;
    W += (long long)blockIdx.z * sW;
    C += (long long)blockIdx.z * sC;
    int m0 = blockIdx.x * 128, n0 = blockIdx.y * 64;
    int tid = threadIdx.x;
    int warp = tid >> 5, lane = tid & 31;
    int wm = warp >> 1, wn = warp & 1;
    int g = lane >> 2, r = lane & 3;
    __shared__ uint32_t sAh[128][20], sAl[128][20], sBh[64][20], sBl[64][20];
    float acc[2][4][4] = {};
    for (int k0 = 0; k0 < K; k0 += 16) {
#pragma unroll
        for (int t = 0; t < 8; t++) {
            int lin = tid + t * 256;
            int row = lin >> 4, col = lin & 15;
            int m = m0 + row, k = k0 + col;
            float v = (m < M && k < K) ? A[(long long)m * K + k] : 0.f;
            uint32_t hi, lo;
            split_tf32(v, hi, lo);
            sAh[row][col] = hi;
            sAl[row][col] = lo;
        }
#pragma unroll
        for (int t = 0; t < 4; t++) {
            int lin = tid + t * 256;
            int row = lin >> 4, col = lin & 15;
            int n = n0 + row, k = k0 + col;
            float v = (n < N && k < K) ? W[(long long)n * K + k] : 0.f;
            uint32_t hi, lo;
            split_tf32(v, hi, lo);
            sBh[row][col] = hi;
            sBl[row][col] = lo;
        }
        __syncthreads();
#pragma unroll
        for (int ks = 0; ks < 2; ks++) {
            int kb = ks * 8;
            uint32_t ah[2][4], al[2][4], bh[4][2], bl[4][2];
#pragma unroll
            for (int mt = 0; mt < 2; mt++) {
                int rb = wm * 32 + mt * 16;
                ah[mt][0] = sAh[rb + g][kb + r];
                ah[mt][1] = sAh[rb + g + 8][kb + r];
                ah[mt][2] = sAh[rb + g][kb + r + 4];
                ah[mt][3] = sAh[rb + g + 8][kb + r + 4];
                al[mt][0] = sAl[rb + g][kb + r];
                al[mt][1] = sAl[rb + g + 8][kb + r];
                al[mt][2] = sAl[rb + g][kb + r + 4];
                al[mt][3] = sAl[rb + g + 8][kb + r + 4];
            }
#pragma unroll
            for (int nt = 0; nt < 4; nt++) {
                int cb = wn * 32 + nt * 8;
                bh[nt][0] = sBh[cb + g][kb + r];
                bh[nt][1] = sBh[cb + g][kb + r + 4];
                bl[nt][0] = sBl[cb + g][kb + r];
                bl[nt][1] = sBl[cb + g][kb + r + 4];
            }
#pragma unroll
            for (int mt = 0; mt < 2; mt++)
#pragma unroll
                for (int nt = 0; nt < 4; nt++) {
                    mma_tf32(acc[mt][nt], ah[mt], bh[nt]);
                    mma_tf32(acc[mt][nt], al[mt], bh[nt]);
                    mma_tf32(acc[mt][nt], ah[mt], bl[nt]);
                }
        }
        __syncthreads();
    }
#pragma unroll
    for (int mt = 0; mt < 2; mt++) {
        int rbase = m0 + wm * 32 + mt * 16;
#pragma unroll
        for (int nt = 0; nt < 4; nt++) {
            int cbase = n0 + wn * 32 + nt * 8 + 2 * r;
#pragma unroll
            for (int e = 0; e < 4; e++) {
                int m = rbase + g + ((e >= 2) ? 8 : 0);
                int n = cbase + (e & 1);
                if (m < M && n < N) {
                    float v = acc[mt][nt][e] * alpha;
                    if (bias) v += bias[n];
                    if (act == 1) v = fmaxf(v, 0.f);
                    if (accum) C[(long long)m * N + n] += v;
                    else       C[(long long)m * N + n] = v;
                }
            }
        }
    }
}

// ---------------- prep kernels ----------------
__global__ void prep_wc(const float* __restrict__ w_tf, const float* __restrict__ b_tf,
                        const float* __restrict__ w_in, const float* __restrict__ b_in) {
    int idx = blockIdx.x * blockDim.x + threadIdx.x;
    if (idx < 4 * D * 128) {
        int s = idx >> 15;
        int rr = idx & 32767;
        int n = rr >> 7;
        int i = rr & 127;
        float acc = 0.f;
        for (int c = 0; c < 128; c++) {
            const float* w3 = w_tf + (c * 128 + i) * 3;
            float coeff;
            if (s == 0)      coeff = w3[0] + w3[1];
            else if (s == 3) coeff = w3[1] + w3[2];
            else             coeff = w3[0] + w3[1] + w3[2];
            acc += w_in[n * 128 + c] * coeff;
        }
        g_Wc[n * 512 + s * 128 + i] = 0.25f * acc;
    }
    if (idx < D) {
        float a = b_in[idx];
        for (int c = 0; c < 128; c++) a += w_in[idx * 128 + c] * b_tf[c];
        g_biasc[idx] = a;
    }
}

// repack w_sm[0] (O,C,3,3) -> [o][tap*256+c]
__global__ void prep_wt(const float* __restrict__ w_sm) {
    int idx = blockIdx.x * blockDim.x + threadIdx.x;
    if (idx >= KP1 * D) return;
    int o = idx / KP1;
    int rr = idx % KP1;
    int tap = rr >> 8;
    int c = rr & 255;
    g_wt[idx] = w_sm[(o * D + c) * 9 + tap];
}

// transpose feat [b][512][4096] -> g_xin [b][4096][512]
__global__ void transposeA(const float* __restrict__ feat) {
    __shared__ float t[32][33];
    int b = blockIdx.z;
    int hw0 = blockIdx.x * 32, k0 = blockIdx.y * 32;
    const float* src = feat + (long long)b * 512 * HW;
    float* dst = g_xin + (long long)b * HW * 512;
    int tx = threadIdx.x, ty = threadIdx.y;
#pragma unroll
    for (int j = 0; j < 4; j++)
        t[ty + j * 8][tx] = src[(long long)(k0 + ty + j * 8) * HW + hw0 + tx];
    __syncthreads();
#pragma unroll
    for (int j = 0; j < 4; j++)
        dst[(long long)(hw0 + ty + j * 8) * 512 + k0 + tx] = t[tx][ty + j * 8];
}

// add sine positional encoding to g_x
__global__ void add_pos() {
    int idx = blockIdx.x * blockDim.x + threadIdx.x;
    if (idx >= 2 * HW * D) return;
    int d = idx & 255;
    int hw = (idx >> 8) & (HW - 1);
    int h = hw >> 6, w = hw & 63;
    int e = (d < 128) ? d : (d - 128);
    int ii = e >> 1;
    float fl = (float)(ii >> 1);
    float dimt = exp2f(fl * 0.415241011861f);  // 10000^(fl/32)
    float coord = (d < 128) ? (float)(h + 1) : (float)(w + 1);
    float arg = coord * (6.2831853071795864769f / (64.f + 1e-6f)) / dimt;
    float pv = (e & 1) ? cosf(arg) : sinf(arg);
    g_x[idx] += pv;
}

// im2col: g_col[b*hw][tap*256+c] = g_y[b][h+dy][w+dx][c] (zero pad)
__global__ void im2col() {
    long long idx = (long long)blockIdx.x * blockDim.x + threadIdx.x;
    if (idx >= (long long)2 * HW * KP1) return;
    int m = (int)(idx / KP1);
    int rr = (int)(idx % KP1);
    int tap = rr >> 8, c = rr & 255;
    int b = m >> 12;
    int h = (m >> 6) & 63, w = m & 63;
    int hh = h + (tap / 3) - 1;
    int ww = w + (tap % 3) - 1;
    float v = 0.f;
    if ((unsigned)hh < 64u && (unsigned)ww < 64u)
        v = g_y[(((long long)b << 12) + (hh << 6) + ww) * D + c];
    g_col[idx] = v;
}

// ---------------- decoder small kernels ----------------
__global__ void init_q(const float* __restrict__ qe, const float* __restrict__ qp) {
    int idx = blockIdx.x * blockDim.x + threadIdx.x;
    if (idx >= 2 * NQ * D) return;
    int qd = idx % (NQ * D);
    g_q[idx] = qe[qd] + qp[qd];
}

__global__ void init_boxes(const float* __restrict__ pbi) {
    int idx = blockIdx.x * blockDim.x + threadIdx.x;
    if (idx < 2 * NQ * 4) g_boxes[idx] = pbi[idx];
}

__global__ void roref_kernel(const float* __restrict__ w_r2, const float* __restrict__ b_r2) {
    int bq = blockIdx.x;
    int tid = threadIdx.x;  // 128
    __shared__ float hrow[256];
    __shared__ float ro[16];
    hrow[tid] = g_h1[bq * 256 + tid];
    hrow[tid + 128] = g_h1[bq * 256 + tid + 128];
    __syncthreads();
    int warp = tid >> 5, lane = tid & 31;
#pragma unroll
    for (int jj = 0; jj < 4; jj++) {
        int j = warp * 4 + jj;
        float s = 0.f;
        for (int k = lane; k < 256; k += 32) s += hrow[k] * w_r2[j * 256 + k];
#pragma unroll
        for (int o = 16; o; o >>= 1) s += __shfl_xor_sync(0xffffffffu, s, o);
        if (lane == 0) ro[j] = tanhf(s + b_r2[j]);
    }
    __syncthreads();
    if (tid < 8) {
        float bx = g_boxes[bq * 4 + 0], by = g_boxes[bq * 4 + 1];
        float rx = fminf(fmaxf(bx + 0.5f * ro[2 * tid + 0], 0.f), 1.f);
        float ry = fminf(fmaxf(by + 0.5f * ro[2 * tid + 1], 0.f), 1.f);
        g_ref[(bq * 8 + tid) * 2 + 0] = rx;
        g_ref[(bq * 8 + tid) * 2 + 1] = ry;
    }
}

__global__ void sample_kernel() {
    int bqp = blockIdx.x;      // 4800
    int c = threadIdx.x;       // 256
    int b = bqp / (NQ * NP);
    float rx = g_ref[bqp * 2 + 0];
    float ry = g_ref[bqp * 2 + 1];
    const float* f = g_f0 + (long long)b * HW * D;
    float* outp = g_flat + (long long)bqp * KP1;
#pragma unroll
    for (int cy = 0; cy < 3; cy++) {
        float oy = (float)(cy - 1);
        float gy = ry * 2.f - 1.f + oy * (2.f / 64.f);
        float yy = fminf(fmaxf((gy + 1.f) * 0.5f * 63.f, 0.f), 63.f);
        float y0f = floorf(yy);
        int y0 = (int)y0f;
        float wy = yy - y0f;
        int y1 = min(y0 + 1, 63);
#pragma unroll
        for (int cx = 0; cx < 3; cx++) {
            float ox = (float)(cx - 1);
            float gx = rx * 2.f - 1.f + ox * (2.f / 64.f);
            float xx = fminf(fmaxf((gx + 1.f) * 0.5f * 63.f, 0.f), 63.f);
            float x0f = floorf(xx);
            int x0 = (int)x0f;
            float wx = xx - x0f;
            int x1 = min(x0 + 1, 63);
            float v00 = f[((y0 << 6) + x0) * D + c];
            float v01 = f[((y0 << 6) + x1) * D + c];
            float v10 = f[((y1 << 6) + x0) * D + c];
            float v11 = f[((y1 << 6) + x1) * D + c];
            float v = v00 * (1.f - wx) * (1.f - wy) + v01 * wx * (1.f - wy)
                    + v10 * (1.f - wx) * wy + v11 * wx * wy;
            outp[(cy * 3 + cx) * D + c] = v;
        }
    }
}

__global__ void kvmean_kernel() {
    int bq = blockIdx.x;   // 600
    int d = threadIdx.x;   // 256
    float s = 0.f;
#pragma unroll
    for (int p = 0; p < 8; p++) s += g_pv2[((long long)bq * 8 + p) * D + d];
    s *= 0.125f;
    g_kv[bq * D + d] = s;
    int b = bq / NQ, qq = bq % NQ;
    g_kvT[((long long)b * D + d) * NQ + qq] = s;
}

__global__ void softmax_kernel() {
    int row = blockIdx.x;  // 600
    float* p = g_sc + (long long)row * NQ;
    int tid = threadIdx.x; // 128
    __shared__ float red[128];
    float m = -1e30f;
    for (int i = tid; i < NQ; i += 128) m = fmaxf(m, p[i]);
    red[tid] = m;
    __syncthreads();
    for (int s = 64; s; s >>= 1) {
        if (tid < s) red[tid] = fmaxf(red[tid], red[tid + s]);
        __syncthreads();
    }
    m = red[0];
    __syncthreads();
    float sum = 0.f;
    for (int i = tid; i < NQ; i += 128) {
        float e = expf(p[i] - m);
        p[i] = e;
        sum += e;
    }
    red[tid] = sum;
    __syncthreads();
    for (int s = 64; s; s >>= 1) {
        if (tid < s) red[tid] += red[tid + s];
        __syncthreads();
    }
    float inv = 1.f / red[0];
    for (int i = tid; i < NQ; i += 128) p[i] *= inv;
}

__global__ void boxupd_kernel(const float* __restrict__ w_b2, const float* __restrict__ b_b2) {
    int bq = blockIdx.x;
    int tid = threadIdx.x;  // 128
    __shared__ float hrow[256];
    hrow[tid] = g_hb[bq * 256 + tid];
    hrow[tid + 128] = g_hb[bq * 256 + tid + 128];
    __syncthreads();
    int warp = tid >> 5, lane = tid & 31;
    float s = 0.f;
    for (int k = lane; k < 256; k += 32) s += hrow[k] * w_b2[warp * 256 + k];
#pragma unroll
    for (int o = 16; o; o >>= 1) s += __shfl_xor_sync(0xffffffffu, s, o);
    if (lane == 0) {
        float delta = 1.f / (1.f + expf(-(s + b_b2[warp])));
        float nb = g_boxes[bq * 4 + warp] + 0.1f * tanhf(delta - 0.5f);
        g_boxes[bq * 4 + warp] = fminf(fmaxf(nb, 0.f), 1.f);
    }
}

__global__ void cls_kernel(const float* __restrict__ w_cls, const float* __restrict__ b_cls,
                           float* __restrict__ out) {
    int bq = blockIdx.x;
    int lane = threadIdx.x;  // 32
    float s = 0.f;
    for (int k = lane; k < 256; k += 32) s += g_q[bq * 256 + k] * w_cls[k];
#pragma unroll
    for (int o = 16; o; o >>= 1) s += __shfl_xor_sync(0xffffffffu, s, o);
    if (lane == 0) out[bq] = s + b_cls[0];
}

__global__ void copy_boxes(float* __restrict__ out) {
    int idx = blockIdx.x * blockDim.x + threadIdx.x;
    if (idx < 2 * NQ * 4) out[600 + idx] = g_boxes[idx];
}

// ---------------- host ----------------
static void gemm(const float* A, const float* W, const float* bias, float* C,
                 int M, int N, int K, float alpha, int act, int accum,
                 int batch, long long sA, long long sW, long long sC) {
    dim3 grid((M + 127) / 128, (N + 63) / 64, batch);
    tc_gemm<<<grid, 256>>>(A, W, bias, C, M, N, K, alpha, act, accum, sA, sW, sC);
}

extern "C" void kernel_launch(void* const* d_in, const int* in_sizes, int n_in,
                              void* d_out, int out_size) {
    const float* feat   = (const float*)d_in[0];
    const float* pbi    = (const float*)d_in[1];
    const float* w_tf   = (const float*)d_in[2];
    const float* b_tf   = (const float*)d_in[3];
    const float* w_in   = (const float*)d_in[4];
    const float* b_in   = (const float*)d_in[5];
    const float* w_lat  = (const float*)d_in[6];
    const float* b_lat  = (const float*)d_in[7];
    const float* w_sm   = (const float*)d_in[8];
    const float* b_sm   = (const float*)d_in[9];
    const float* q_embed= (const float*)d_in[10];
    const float* q_pos  = (const float*)d_in[11];
    const float* Wq     = (const float*)d_in[12];
    const float* bqv    = (const float*)d_in[13];
    const float* Wo     = (const float*)d_in[14];
    const float* bo     = (const float*)d_in[15];
    const float* Wp1    = (const float*)d_in[16];
    const float* bp1    = (const float*)d_in[17];
    const float* Wp2    = (const float*)d_in[18];
    const float* bp2    = (const float*)d_in[19];
    const float* w_r1   = (const float*)d_in[20];
    const float* b_r1   = (const float*)d_in[21];
    const float* w_r2   = (const float*)d_in[22];
    const float* b_r2   = (const float*)d_in[23];
    const float* w_b1   = (const float*)d_in[24];
    const float* b_b1   = (const float*)d_in[25];
    const float* w_b2   = (const float*)d_in[26];
    const float* b_b2   = (const float*)d_in[27];
    const float* w_cls  = (const float*)d_in[28];
    const float* b_cls  = (const float*)d_in[29];
    float* out = (float*)d_out;

    float *p_Wc, *p_biasc, *p_wt, *p_xin, *p_x, *p_y, *p_col, *p_f0;
    float *p_q, *p_h1, *p_flat, *p_pv1, *p_pv2, *p_kv, *p_kvT, *p_qp, *p_sc, *p_ao, *p_hb;
    cudaGetSymbolAddress((void**)&p_Wc, g_Wc);
    cudaGetSymbolAddress((void**)&p_biasc, g_biasc);
    cudaGetSymbolAddress((void**)&p_wt, g_wt);
    cudaGetSymbolAddress((void**)&p_xin, g_xin);
    cudaGetSymbolAddress((void**)&p_x, g_x);
    cudaGetSymbolAddress((void**)&p_y, g_y);
    cudaGetSymbolAddress((void**)&p_col, g_col);
    cudaGetSymbolAddress((void**)&p_f0, g_f0);
    cudaGetSymbolAddress((void**)&p_q, g_q);
    cudaGetSymbolAddress((void**)&p_h1, g_h1);
    cudaGetSymbolAddress((void**)&p_flat, g_flat);
    cudaGetSymbolAddress((void**)&p_pv1, g_pv1);
    cudaGetSymbolAddress((void**)&p_pv2, g_pv2);
    cudaGetSymbolAddress((void**)&p_kv, g_kv);
    cudaGetSymbolAddress((void**)&p_kvT, g_kvT);
    cudaGetSymbolAddress((void**)&p_qp, g_qp);
    cudaGetSymbolAddress((void**)&p_sc, g_sc);
    cudaGetSymbolAddress((void**)&p_ao, g_ao);
    cudaGetSymbolAddress((void**)&p_hb, g_hb);

    // backbone (only scale-1 FPN branch is live)
    prep_wc<<<(4 * D * 128 + 255) / 256, 256>>>(w_tf, b_tf, w_in, b_in);
    prep_wt<<<(KP1 * D + 255) / 256, 256>>>(w_sm);
    transposeA<<<dim3(128, 16, 2), dim3(32, 8)>>>(feat);
    gemm(p_xin, p_Wc, p_biasc, p_x, 2 * HW, D, 512, 1.f, 0, 0, 1, 0, 0, 0);
    add_pos<<<(2 * HW * D + 255) / 256, 256>>>();
    gemm(p_x, w_lat, b_lat, p_y, 2 * HW, D, D, 1.f, 0, 0, 1, 0, 0, 0);
    im2col<<<(int)(((long long)2 * HW * KP1 + 255) / 256), 256>>>();
    gemm(p_col, p_wt, b_sm, p_f0, 2 * HW, D, KP1, 1.f, 0, 0, 1, 0, 0, 0);

    init_q<<<(2 * NQ * D + 255) / 256, 256>>>(q_embed, q_pos);
    init_boxes<<<(2 * NQ * 4 + 255) / 256, 256>>>(pbi);

    const float inv_sqrt_d = 0.0625f;  // 1/sqrt(256)
    for (int l = 0; l < NLAY; l++) {
        gemm(p_q, w_r1, b_r1, p_h1, 2 * NQ, D, D, 1.f, 1, 0, 1, 0, 0, 0);
        roref_kernel<<<2 * NQ, 128>>>(w_r2, b_r2);
        sample_kernel<<<2 * NQ * NP, 256>>>();
        gemm(p_flat, Wp1 + (long long)l * D * KP1, bp1 + l * D, p_pv1,
             2 * NQ * NP, D, KP1, 1.f, 1, 0, 1, 0, 0, 0);
        gemm(p_pv1, Wp2 + (long long)l * D * D, bp2 + l * D, p_pv2,
             2 * NQ * NP, D, D, 1.f, 0, 0, 1, 0, 0, 0);
        kvmean_kernel<<<2 * NQ, 256>>>();
        gemm(p_q, Wq + (long long)l * D * D, bqv + l * D, p_qp,
             2 * NQ, D, D, 1.f, 0, 0, 1, 0, 0, 0);
        gemm(p_qp, p_kv, nullptr, p_sc, NQ, NQ, D, inv_sqrt_d, 0, 0,
             2, (long long)NQ * D, (long long)NQ * D, (long long)NQ * NQ);
        softmax_kernel<<<2 * NQ, 128>>>();
        gemm(p_sc, p_kvT, nullptr, p_ao, NQ, D, NQ, 1.f, 0, 0,
             2, (long long)NQ * NQ, (long long)D * NQ, (long long)NQ * D);
        gemm(p_ao, Wo + (long long)l * D * D, bo + l * D, p_q,
             2 * NQ, D, D, 1.f, 0, 1 /*accum*/, 1, 0, 0, 0);
        gemm(p_q, w_b1, b_b1, p_hb, 2 * NQ, D, D, 1.f, 1, 0, 1, 0, 0, 0);
        boxupd_kernel<<<2 * NQ, 128>>>(w_b2, b_b2);
    }

    cls_kernel<<<2 * NQ, 32>>>(w_cls, b_cls, out);
    copy_boxes<<<(2 * NQ * 4 + 255) / 256, 256>>>(out);
}

// round 3
// speedup vs baseline: 1.4990x; 1.1313x over previous
#include <cuda_runtime.h>
#include <math.h>
#include <stdint.h>

#define D 256
#define HW 4096
#define NQ 300
#define NP 8
#define KP1 2304
#define NLAY 6

// ---------------- scratch (device globals; no allocation) ----------------
__device__ float g_Wc[D * 512];
__device__ float g_biasc[D];
__device__ float g_wt[KP1 * D];          // conv weights [o][tap*256+c]
__device__ float g_w12[NLAY * 512 * D];  // [l][n(512)][k]  n<256: w_r1, else Wq[l]
__device__ float g_b12[NLAY * 512];
__device__ float g_xin[2 * HW * 512];    // transposed stageA input
__device__ float g_x[2 * HW * D];
__device__ float g_y[2 * HW * D];
__device__ float g_f0[2 * HW * D];
__device__ float g_q[2 * NQ * D];
__device__ float g_h1[2 * NQ * 512];     // cols 0-255: relu h1, 256-511: qp
__device__ float g_ref[2 * NQ * NP * 2];
__device__ float g_flat[2 * NQ * NP * KP1];
__device__ float g_pv1[2 * NQ * NP * D];
__device__ float g_pvm[2 * NQ * D];
__device__ float g_kv[2 * NQ * D];
__device__ float g_ao[2 * NQ * D];
__device__ float g_hb[2 * NQ * D];
__device__ float g_boxes[2 * NQ * 4];

// ---------------- tf32 helpers ----------------
__device__ __forceinline__ uint32_t f2tf32(float f) {
    uint32_t u;
    asm("cvt.rna.tf32.f32 %0, %1;" : "=r"(u) : "f"(f));
    return u;
}
__device__ __forceinline__ void split_tf32(float v, uint32_t& hi, uint32_t& lo) {
    hi = f2tf32(v);
    float r = v - __uint_as_float(hi);
    lo = f2tf32(r);
}
__device__ __forceinline__ void mma_tf32(float* c, const uint32_t* a, const uint32_t* b) {
    asm volatile(
        "mma.sync.aligned.m16n8k8.row.col.f32.tf32.tf32.f32 "
        "{%0,%1,%2,%3},{%4,%5,%6,%7},{%8,%9},{%0,%1,%2,%3};"
        : "+f"(c[0]), "+f"(c[1]), "+f"(c[2]), "+f"(c[3])
        : "r"(a[0]), "r"(a[1]), "r"(a[2]), "r"(a[3]), "r"(b[0]), "r"(b[1]));
}

// ---------------- cp.async helpers ----------------
__device__ __forceinline__ void cp16(void* dst, const void* src, int bytes) {
    uint32_t d = (uint32_t)__cvta_generic_to_shared(dst);
    asm volatile("cp.async.ca.shared.global [%0], [%1], 16, %2;\n" ::"r"(d), "l"(src), "r"(bytes));
}
__device__ __forceinline__ void cp_commit() { asm volatile("cp.async.commit_group;\n"); }
__device__ __forceinline__ void cp_wait1() { asm volatile("cp.async.wait_group 1;\n"); }
__device__ __forceinline__ void cp_wait0() { asm volatile("cp.async.wait_group 0;\n"); }

// ---------------- pipelined tensor-core GEMM ----------------
// C[M,N] = epi(alpha*A[M,K] @ W[N,K]^T + bias)
// mode 0: A normal row-major (lda=K). mode 1: implicit im2col from g_y layout (M=8192,K=2304).
// act: 0 none, 1 relu, 2 relu only for n<256. pos: add sine positional enc. accum: +=.
__global__ void __launch_bounds__(256, 2)
tc_gemm2(const float* __restrict__ A, const float* __restrict__ W,
         const float* __restrict__ bias, float* __restrict__ C,
         int M, int N, int K, float alpha, int act, int accum, int mode, int pos) {
    __shared__ float sA[2][128][20];
    __shared__ float sB[2][64][20];
    int m0 = blockIdx.x * 128, n0 = blockIdx.y * 64;
    int tid = threadIdx.x;
    int warp = tid >> 5, lane = tid & 31;
    int wm = warp >> 1, wn = warp & 1;
    int g = lane >> 2, r = lane & 3;
    float acc[2][4][4] = {};
    int nk = K >> 4;

    auto load = [&](int s, int k0) {
#pragma unroll
        for (int t = 0; t < 2; t++) {
            int idx = tid + t * 256;
            int row = idx >> 2, j = idx & 3;
            int m = m0 + row;
            const float* src = A;
            int bytes = 0;
            if (mode == 0) {
                if (m < M) { src = A + (long long)m * K + k0 + j * 4; bytes = 16; }
            } else {
                int tap = k0 >> 8;
                int dy = tap / 3 - 1, dx = tap % 3 - 1;
                int h = (m >> 6) & 63, w = m & 63;
                int hh = h + dy, ww = w + dx;
                if ((unsigned)hh < 64u && (unsigned)ww < 64u) {
                    src = A + ((long long)(m + dy * 64 + dx)) * 256 + (k0 & 255) + j * 4;
                    bytes = 16;
                }
            }
            cp16(&sA[s][row][j * 4], src, bytes);
        }
        {
            int row = tid >> 2, j = tid & 3;
            int n = n0 + row;
            const float* src = W;
            int bytes = 0;
            if (n < N) { src = W + (long long)n * K + k0 + j * 4; bytes = 16; }
            cp16(&sB[s][row][j * 4], src, bytes);
        }
        cp_commit();
    };

    load(0, 0);
    for (int kt = 0; kt < nk; kt++) {
        if (kt + 1 < nk) { load((kt + 1) & 1, (kt + 1) << 4); cp_wait1(); }
        else cp_wait0();
        __syncthreads();
        int s = kt & 1;
#pragma unroll
        for (int ks = 0; ks < 2; ks++) {
            int kb = ks * 8;
            uint32_t ah[2][4], al[2][4], bh[4][2], bl[4][2];
#pragma unroll
            for (int mt = 0; mt < 2; mt++) {
                int rb = wm * 32 + mt * 16;
                float a0 = sA[s][rb + g][kb + r];
                float a1 = sA[s][rb + g + 8][kb + r];
                float a2 = sA[s][rb + g][kb + r + 4];
                float a3 = sA[s][rb + g + 8][kb + r + 4];
                split_tf32(a0, ah[mt][0], al[mt][0]);
                split_tf32(a1, ah[mt][1], al[mt][1]);
                split_tf32(a2, ah[mt][2], al[mt][2]);
                split_tf32(a3, ah[mt][3], al[mt][3]);
            }
#pragma unroll
            for (int nt = 0; nt < 4; nt++) {
                int cb = wn * 32 + nt * 8;
                float b0 = sB[s][cb + g][kb + r];
                float b1 = sB[s][cb + g][kb + r + 4];
                split_tf32(b0, bh[nt][0], bl[nt][0]);
                split_tf32(b1, bh[nt][1], bl[nt][1]);
            }
#pragma unroll
            for (int mt = 0; mt < 2; mt++)
#pragma unroll
                for (int nt = 0; nt < 4; nt++) {
                    mma_tf32(acc[mt][nt], ah[mt], bh[nt]);
                    mma_tf32(acc[mt][nt], al[mt], bh[nt]);
                    mma_tf32(acc[mt][nt], ah[mt], bl[nt]);
                }
        }
        __syncthreads();
    }
#pragma unroll
    for (int mt = 0; mt < 2; mt++) {
        int rbase = m0 + wm * 32 + mt * 16;
#pragma unroll
        for (int nt = 0; nt < 4; nt++) {
            int cbase = n0 + wn * 32 + nt * 8 + 2 * r;
#pragma unroll
            for (int e = 0; e < 4; e++) {
                int m = rbase + g + ((e >= 2) ? 8 : 0);
                int n = cbase + (e & 1);
                if (m < M && n < N) {
                    float v = acc[mt][nt][e] * alpha;
                    if (bias) v += bias[n];
                    if (act == 1 || (act == 2 && n < 256)) v = fmaxf(v, 0.f);
                    if (pos) {
                        int hw = m & 4095;
                        int h = hw >> 6, w = hw & 63;
                        int e2 = (n < 128) ? n : (n - 128);
                        float fl = (float)((e2 >> 1) >> 1);
                        float dimt = exp2f(fl * 0.415241011861f);  // 10000^(fl/32)
                        float coord = (n < 128) ? (float)(h + 1) : (float)(w + 1);
                        float arg = coord * (6.2831853071795864769f / (64.f + 1e-6f)) / dimt;
                        v += (e2 & 1) ? cosf(arg) : sinf(arg);
                    }
                    if (accum) C[(long long)m * N + n] += v;
                    else       C[(long long)m * N + n] = v;
                }
            }
        }
    }
}

// ---------------- prep kernels ----------------
__global__ void prep_wc(const float* __restrict__ w_tf, const float* __restrict__ b_tf,
                        const float* __restrict__ w_in, const float* __restrict__ b_in) {
    int idx = blockIdx.x * blockDim.x + threadIdx.x;
    if (idx < 4 * D * 128) {
        int s = idx >> 15;
        int rr = idx & 32767;
        int n = rr >> 7;
        int i = rr & 127;
        float acc = 0.f;
        for (int c = 0; c < 128; c++) {
            const float* w3 = w_tf + (c * 128 + i) * 3;
            float coeff;
            if (s == 0)      coeff = w3[0] + w3[1];
            else if (s == 3) coeff = w3[1] + w3[2];
            else             coeff = w3[0] + w3[1] + w3[2];
            acc += w_in[n * 128 + c] * coeff;
        }
        g_Wc[n * 512 + s * 128 + i] = 0.25f * acc;
    }
    if (idx < D) {
        float a = b_in[idx];
        for (int c = 0; c < 128; c++) a += w_in[idx * 128 + c] * b_tf[c];
        g_biasc[idx] = a;
    }
}

__global__ void prep_wt(const float* __restrict__ w_sm) {
    int idx = blockIdx.x * blockDim.x + threadIdx.x;
    if (idx >= KP1 * D) return;
    int o = idx / KP1;
    int rr = idx % KP1;
    int tap = rr >> 8;
    int c = rr & 255;
    g_wt[idx] = w_sm[(o * D + c) * 9 + tap];
}

__global__ void prep_w12(const float* __restrict__ w_r1, const float* __restrict__ b_r1,
                         const float* __restrict__ Wq, const float* __restrict__ bq) {
    int idx = blockIdx.x * blockDim.x + threadIdx.x;
    if (idx < NLAY * 512 * D) {
        int l = idx / (512 * D);
        int rr = idx % (512 * D);
        int n = rr >> 8;
        int k = rr & 255;
        g_w12[idx] = (n < 256) ? w_r1[n * 256 + k] : Wq[(l * 256 + (n - 256)) * 256 + k];
    }
    if (idx < NLAY * 512) {
        int l = idx / 512, n = idx % 512;
        g_b12[idx] = (n < 256) ? b_r1[n] : bq[l * 256 + n - 256];
    }
}

// transpose feat [b][512][4096] -> g_xin [b][4096][512]
__global__ void transposeA(const float* __restrict__ feat) {
    __shared__ float t[32][33];
    int b = blockIdx.z;
    int hw0 = blockIdx.x * 32, k0 = blockIdx.y * 32;
    const float* src = feat + (long long)b * 512 * HW;
    float* dst = g_xin + (long long)b * HW * 512;
    int tx = threadIdx.x, ty = threadIdx.y;
#pragma unroll
    for (int j = 0; j < 4; j++)
        t[ty + j * 8][tx] = src[(long long)(k0 + ty + j * 8) * HW + hw0 + tx];
    __syncthreads();
#pragma unroll
    for (int j = 0; j < 4; j++)
        dst[(long long)(hw0 + ty + j * 8) * 512 + k0 + tx] = t[tx][ty + j * 8];
}

// ---------------- decoder small kernels ----------------
__global__ void init_q(const float* __restrict__ qe, const float* __restrict__ qp) {
    int idx = blockIdx.x * blockDim.x + threadIdx.x;
    if (idx >= 2 * NQ * D) return;
    int qd = idx % (NQ * D);
    g_q[idx] = qe[qd] + qp[qd];
}

__global__ void init_boxes(const float* __restrict__ pbi) {
    int idx = blockIdx.x * blockDim.x + threadIdx.x;
    if (idx < 2 * NQ * 4) g_boxes[idx] = pbi[idx];
}

__global__ void roref_kernel(const float* __restrict__ w_r2, const float* __restrict__ b_r2) {
    int bq = blockIdx.x;
    int tid = threadIdx.x;  // 128
    __shared__ float hrow[256];
    __shared__ float ro[16];
    hrow[tid] = g_h1[bq * 512 + tid];
    hrow[tid + 128] = g_h1[bq * 512 + tid + 128];
    __syncthreads();
    int warp = tid >> 5, lane = tid & 31;
#pragma unroll
    for (int jj = 0; jj < 4; jj++) {
        int j = warp * 4 + jj;
        float s = 0.f;
        for (int k = lane; k < 256; k += 32) s += hrow[k] * w_r2[j * 256 + k];
#pragma unroll
        for (int o = 16; o; o >>= 1) s += __shfl_xor_sync(0xffffffffu, s, o);
        if (lane == 0) ro[j] = tanhf(s + b_r2[j]);
    }
    __syncthreads();
    if (tid < 8) {
        float bx = g_boxes[bq * 4 + 0], by = g_boxes[bq * 4 + 1];
        float rx = fminf(fmaxf(bx + 0.5f * ro[2 * tid + 0], 0.f), 1.f);
        float ry = fminf(fmaxf(by + 0.5f * ro[2 * tid + 1], 0.f), 1.f);
        g_ref[(bq * 8 + tid) * 2 + 0] = rx;
        g_ref[(bq * 8 + tid) * 2 + 1] = ry;
    }
}

__global__ void sample_kernel() {
    int bqp = blockIdx.x;      // 4800
    int c = threadIdx.x;       // 256
    int b = bqp / (NQ * NP);
    float rx = g_ref[bqp * 2 + 0];
    float ry = g_ref[bqp * 2 + 1];
    const float* f = g_f0 + (long long)b * HW * D;
    float* outp = g_flat + (long long)bqp * KP1;
#pragma unroll
    for (int cy = 0; cy < 3; cy++) {
        float oy = (float)(cy - 1);
        float gy = ry * 2.f - 1.f + oy * (2.f / 64.f);
        float yy = fminf(fmaxf((gy + 1.f) * 0.5f * 63.f, 0.f), 63.f);
        float y0f = floorf(yy);
        int y0 = (int)y0f;
        float wy = yy - y0f;
        int y1 = min(y0 + 1, 63);
#pragma unroll
        for (int cx = 0; cx < 3; cx++) {
            float ox = (float)(cx - 1);
            float gx = rx * 2.f - 1.f + ox * (2.f / 64.f);
            float xx = fminf(fmaxf((gx + 1.f) * 0.5f * 63.f, 0.f), 63.f);
            float x0f = floorf(xx);
            int x0 = (int)x0f;
            float wx = xx - x0f;
            int x1 = min(x0 + 1, 63);
            float v00 = f[((y0 << 6) + x0) * D + c];
            float v01 = f[((y0 << 6) + x1) * D + c];
            float v10 = f[((y1 << 6) + x0) * D + c];
            float v11 = f[((y1 << 6) + x1) * D + c];
            float v = v00 * (1.f - wx) * (1.f - wy) + v01 * wx * (1.f - wy)
                    + v10 * (1.f - wx) * wy + v11 * wx * wy;
            outp[(cy * 3 + cx) * D + c] = v;
        }
    }
}

__global__ void pvmean_kernel() {
    int bq = blockIdx.x;   // 600
    int d = threadIdx.x;   // 256
    float s = 0.f;
#pragma unroll
    for (int p = 0; p < 8; p++) s += g_pv1[((long long)bq * 8 + p) * D + d];
    g_pvm[bq * D + d] = s * 0.125f;
}

// ---------------- fused attention: scores + softmax + weighted sum ----------------
// grid (38, 2), block 256 (8 warps, 1 query/warp)
__global__ void attn_kernel() {
    __shared__ float qs[8][260];
    __shared__ float kvs[16][264];
    __shared__ float tr[8][528];
    int b = blockIdx.y, qt = blockIdx.x;
    int tid = threadIdx.x;
    int warp = tid >> 5, lane = tid & 31;
    const float* kvb = g_kv + (long long)b * NQ * D;
    // load 8 query rows (qp part of g_h1)
#pragma unroll
    for (int i = 0; i < 8; i++) {
        int idx = tid + i * 256;
        int qi = idx >> 8, c = idx & 255;
        int q = qt * 8 + qi;
        qs[qi][c] = (q < NQ) ? g_h1[((long long)b * NQ + q) * 512 + 256 + c] : 0.f;
    }
    float sc[19];
    // pass 1: scores
#pragma unroll
    for (int kt = 0; kt < 19; kt++) {
        __syncthreads();
#pragma unroll
        for (int i = 0; i < 16; i++) {
            int idx = tid + i * 256;
            int j = idx >> 8, c = idx & 255;
            int key = kt * 16 + j;
            kvs[j][c] = (key < NQ) ? kvb[(long long)key * D + c] : 0.f;
        }
        __syncthreads();
        float p[16] = {};
#pragma unroll
        for (int i = 0; i < 8; i++) {
            float qv = qs[warp][i * 32 + lane];
#pragma unroll
            for (int j = 0; j < 16; j++) p[j] += qv * kvs[j][i * 32 + lane];
        }
#pragma unroll
        for (int j = 0; j < 16; j++) tr[warp][j * 33 + lane] = p[j];
        __syncwarp();
        if (lane < 16) {
            float s = 0.f;
#pragma unroll
            for (int x = 0; x < 32; x++) s += tr[warp][lane * 33 + x];
            sc[kt] = (kt * 16 + lane < NQ) ? s * 0.0625f : -1e30f;
        }
        __syncwarp();
    }
    // softmax over 300 scores (lanes 0..15 hold 19 each)
    float m = -1e30f;
    if (lane < 16) {
#pragma unroll
        for (int kt = 0; kt < 19; kt++) m = fmaxf(m, sc[kt]);
    }
#pragma unroll
    for (int o = 16; o; o >>= 1) m = fmaxf(m, __shfl_xor_sync(0xffffffffu, m, o));
    float sum = 0.f;
    if (lane < 16) {
#pragma unroll
        for (int kt = 0; kt < 19; kt++) {
            float e = expf(sc[kt] - m);
            sc[kt] = e;
            sum += e;
        }
    }
#pragma unroll
    for (int o = 16; o; o >>= 1) sum += __shfl_xor_sync(0xffffffffu, sum, o);
    float inv = 1.f / sum;
    if (lane < 16) {
#pragma unroll
        for (int kt = 0; kt < 19; kt++) tr[warp][kt * 16 + lane] = sc[kt] * inv;
    }
    __syncwarp();
    // pass 2: out = attn @ kv
    float out[8] = {};
#pragma unroll
    for (int kt = 0; kt < 19; kt++) {
        __syncthreads();
#pragma unroll
        for (int i = 0; i < 16; i++) {
            int idx = tid + i * 256;
            int j = idx >> 8, c = idx & 255;
            int key = kt * 16 + j;
            kvs[j][c] = (key < NQ) ? kvb[(long long)key * D + c] : 0.f;
        }
        __syncthreads();
#pragma unroll
        for (int j = 0; j < 16; j++) {
            float a = tr[warp][kt * 16 + j];
#pragma unroll
            for (int i = 0; i < 8; i++) out[i] += a * kvs[j][i * 32 + lane];
        }
    }
    int q = qt * 8 + warp;
    if (q < NQ) {
#pragma unroll
        for (int i = 0; i < 8; i++)
            g_ao[((long long)b * NQ + q) * D + i * 32 + lane] = out[i];
    }
}

__global__ void boxupd_kernel(const float* __restrict__ w_b2, const float* __restrict__ b_b2) {
    int bq = blockIdx.x;
    int tid = threadIdx.x;  // 128
    __shared__ float hrow[256];
    hrow[tid] = g_hb[bq * 256 + tid];
    hrow[tid + 128] = g_hb[bq * 256 + tid + 128];
    __syncthreads();
    int warp = tid >> 5, lane = tid & 31;
    float s = 0.f;
    for (int k = lane; k < 256; k += 32) s += hrow[k] * w_b2[warp * 256 + k];
#pragma unroll
    for (int o = 16; o; o >>= 1) s += __shfl_xor_sync(0xffffffffu, s, o);
    if (lane == 0) {
        float delta = 1.f / (1.f + expf(-(s + b_b2[warp])));
        float nb = g_boxes[bq * 4 + warp] + 0.1f * tanhf(delta - 0.5f);
        g_boxes[bq * 4 + warp] = fminf(fmaxf(nb, 0.f), 1.f);
    }
}

__global__ void cls_kernel(const float* __restrict__ w_cls, const float* __restrict__ b_cls,
                           float* __restrict__ out) {
    int bq = blockIdx.x;
    int lane = threadIdx.x;  // 32
    float s = 0.f;
    for (int k = lane; k < 256; k += 32) s += g_q[bq * 256 + k] * w_cls[k];
#pragma unroll
    for (int o = 16; o; o >>= 1) s += __shfl_xor_sync(0xffffffffu, s, o);
    if (lane == 0) out[bq] = s + b_cls[0];
}

__global__ void copy_boxes(float* __restrict__ out) {
    int idx = blockIdx.x * blockDim.x + threadIdx.x;
    if (idx < 2 * NQ * 4) out[600 + idx] = g_boxes[idx];
}

// ---------------- host ----------------
static void gemm(const float* A, const float* W, const float* bias, float* C,
                 int M, int N, int K, float alpha, int act, int accum, int mode, int pos) {
    dim3 grid((M + 127) / 128, (N + 63) / 64);
    tc_gemm2<<<grid, 256>>>(A, W, bias, C, M, N, K, alpha, act, accum, mode, pos);
}

extern "C" void kernel_launch(void* const* d_in, const int* in_sizes, int n_in,
                              void* d_out, int out_size) {
    const float* feat   = (const float*)d_in[0];
    const float* pbi    = (const float*)d_in[1];
    const float* w_tf   = (const float*)d_in[2];
    const float* b_tf   = (const float*)d_in[3];
    const float* w_in   = (const float*)d_in[4];
    const float* b_in   = (const float*)d_in[5];
    const float* w_lat  = (const float*)d_in[6];
    const float* b_lat  = (const float*)d_in[7];
    const float* w_sm   = (const float*)d_in[8];
    const float* b_sm   = (const float*)d_in[9];
    const float* q_embed= (const float*)d_in[10];
    const float* q_pos  = (const float*)d_in[11];
    const float* Wq     = (const float*)d_in[12];
    const float* bqv    = (const float*)d_in[13];
    const float* Wo     = (const float*)d_in[14];
    const float* bo     = (const float*)d_in[15];
    const float* Wp1    = (const float*)d_in[16];
    const float* bp1    = (const float*)d_in[17];
    const float* Wp2    = (const float*)d_in[18];
    const float* bp2    = (const float*)d_in[19];
    const float* w_r1   = (const float*)d_in[20];
    const float* b_r1   = (const float*)d_in[21];
    const float* w_r2   = (const float*)d_in[22];
    const float* b_r2   = (const float*)d_in[23];
    const float* w_b1   = (const float*)d_in[24];
    const float* b_b1   = (const float*)d_in[25];
    const float* w_b2   = (const float*)d_in[26];
    const float* b_b2   = (const float*)d_in[27];
    const float* w_cls  = (const float*)d_in[28];
    const float* b_cls  = (const float*)d_in[29];
    float* out = (float*)d_out;

    float *p_Wc, *p_biasc, *p_wt, *p_w12, *p_b12, *p_xin, *p_x, *p_y, *p_f0;
    float *p_q, *p_h1, *p_flat, *p_pv1, *p_pvm, *p_kv, *p_ao, *p_hb;
    cudaGetSymbolAddress((void**)&p_Wc, g_Wc);
    cudaGetSymbolAddress((void**)&p_biasc, g_biasc);
    cudaGetSymbolAddress((void**)&p_wt, g_wt);
    cudaGetSymbolAddress((void**)&p_w12, g_w12);
    cudaGetSymbolAddress((void**)&p_b12, g_b12);
    cudaGetSymbolAddress((void**)&p_xin, g_xin);
    cudaGetSymbolAddress((void**)&p_x, g_x);
    cudaGetSymbolAddress((void**)&p_y, g_y);
    cudaGetSymbolAddress((void**)&p_f0, g_f0);
    cudaGetSymbolAddress((void**)&p_q, g_q);
    cudaGetSymbolAddress((void**)&p_h1, g_h1);
    cudaGetSymbolAddress((void**)&p_flat, g_flat);
    cudaGetSymbolAddress((void**)&p_pv1, g_pv1);
    cudaGetSymbolAddress((void**)&p_pvm, g_pvm);
    cudaGetSymbolAddress((void**)&p_kv, g_kv);
    cudaGetSymbolAddress((void**)&p_ao, g_ao);
    cudaGetSymbolAddress((void**)&p_hb, g_hb);

    // backbone (only scale-1 FPN branch is live)
    prep_wc<<<(4 * D * 128 + 255) / 256, 256>>>(w_tf, b_tf, w_in, b_in);
    prep_wt<<<(KP1 * D + 255) / 256, 256>>>(w_sm);
    prep_w12<<<(NLAY * 512 * D + 255) / 256, 256>>>(w_r1, b_r1, Wq, bqv);
    transposeA<<<dim3(128, 16, 2), dim3(32, 8)>>>(feat);
    gemm(p_xin, p_Wc, p_biasc, p_x, 2 * HW, D, 512, 1.f, 0, 0, 0, 1 /*pos*/);
    gemm(p_x, w_lat, b_lat, p_y, 2 * HW, D, D, 1.f, 0, 0, 0, 0);
    gemm(p_y, p_wt, b_sm, p_f0, 2 * HW, D, KP1, 1.f, 0, 0, 1 /*conv*/, 0);

    init_q<<<(2 * NQ * D + 255) / 256, 256>>>(q_embed, q_pos);
    init_boxes<<<(2 * NQ * 4 + 255) / 256, 256>>>(pbi);

    for (int l = 0; l < NLAY; l++) {
        gemm(p_q, p_w12 + (long long)l * 512 * D, p_b12 + l * 512, p_h1,
             2 * NQ, 512, D, 1.f, 2 /*relu n<256*/, 0, 0, 0);
        roref_kernel<<<2 * NQ, 128>>>(w_r2, b_r2);
        sample_kernel<<<2 * NQ * NP, 256>>>();
        gemm(p_flat, Wp1 + (long long)l * D * KP1, bp1 + l * D, p_pv1,
             2 * NQ * NP, D, KP1, 1.f, 1, 0, 0, 0);
        pvmean_kernel<<<2 * NQ, 256>>>();
        gemm(p_pvm, Wp2 + (long long)l * D * D, bp2 + l * D, p_kv,
             2 * NQ, D, D, 1.f, 0, 0, 0, 0);
        attn_kernel<<<dim3(38, 2), 256>>>();
        gemm(p_ao, Wo + (long long)l * D * D, bo + l * D, p_q,
             2 * NQ, D, D, 1.f, 0, 1 /*accum*/, 0, 0);
        gemm(p_q, w_b1, b_b1, p_hb, 2 * NQ, D, D, 1.f, 1, 0, 0, 0);
        boxupd_kernel<<<2 * NQ, 128>>>(w_b2, b_b2);
    }

    cls_kernel<<<2 * NQ, 32>>>(w_cls, b_cls, out);
    copy_boxes<<<(2 * NQ * 4 + 255) / 256, 256>>>(out);
}